// round 1
// baseline (speedup 1.0000x reference)
#include <cuda_runtime.h>
#include <math.h>
#include <stdint.h>

// ============================================================================
// Problem: pairwise |x_i - x_j| -> 4x(1x1conv + BN(train) + LeakyReLU)
//          -> linear -> softmax(axis=2) -> top-K scatter mask.
// Exploit symmetry: logits[b,i,j] == logits[b,j,i]; compute upper triangle only.
// ============================================================================

namespace cfg {
constexpr int B = 8, V = 201, D = 256, H = 128;
constexpr int T = V * (V + 1) / 2;     // 20301 triangle positions per batch
constexpr int NTRI = B * T;            // 162408 rows actually computed
constexpr int NFULL = B * V * V;       // 323208 positions for BN statistics
constexpr int KTOP = 100;
constexpr float EPS = 1e-5f;
constexpr float SLOPE = 0.01f;
}

// Scratch (static device globals -- no allocations allowed)
__device__ float  g_bufA[(size_t)cfg::NTRI * 256];
__device__ float  g_bufB[(size_t)cfg::NTRI * 256];
__device__ float  g_logits[cfg::NTRI];
__device__ double g_sum[4][256];
__device__ double g_sumsq[4][256];
__device__ float  g_scale[4][256];
__device__ float  g_shift[4][256];
__device__ int2   g_tri[cfg::T];

__device__ __forceinline__ float lrelu(float v) {
    return v >= 0.f ? v : cfg::SLOPE * v;
}

// ---------------------------------------------------------------------------
__global__ void k_init() {
    int t = blockIdx.x * blockDim.x + threadIdx.x;
    if (t < 1024) { ((double*)g_sum)[t] = 0.0; ((double*)g_sumsq)[t] = 0.0; }
}

// Build triangle index table: t -> (i, j), i <= j, row-major upper triangle.
__global__ void k_tri() {
    int i = blockIdx.x;
    int base = i * cfg::V - (i * (i - 1)) / 2;
    for (int j = i + threadIdx.x; j < cfg::V; j += blockDim.x)
        g_tri[base + (j - i)] = make_int2(i, j);
}

// ---------------------------------------------------------------------------
// Fused GEMM: out[r, n] = sum_k A(r,k) * W[n,k] + bias[n]
//   MODE 0: A(r,k) = |x[b,i,k] - x[b,j,k]|          (layer 0, in = x)
//   MODE 1: A(r,k) = leaky(in[r,k]*scale[k]+shift[k]) (folded prev-layer BN)
// Also accumulates weighted per-channel sum / sumsq (weight 2 off-diag, 1 diag)
// for this layer's BatchNorm over the FULL (B,V,V) grid.
// ---------------------------------------------------------------------------
template<int CIN, int COUT, int MODE>
__global__ __launch_bounds__(256, 2)
void k_gemm(const float* __restrict__ in, const float* __restrict__ W,
            const float* __restrict__ bias,
            const float* __restrict__ scale, const float* __restrict__ shift,
            float* __restrict__ out,
            double* __restrict__ osum, double* __restrict__ osumsq)
{
    using namespace cfg;
    constexpr int BM = 128, BN = 128, BK = 8;
    __shared__ float sA[BK][BM];
    __shared__ float sB[BK][BN];
    __shared__ float wrow[BM];
    __shared__ float red[16][BN];

    const int tid  = threadIdx.x;
    const int row0 = blockIdx.x * BM;
    const int n0   = blockIdx.y * BN;

    // Loader mapping: thread t loads row (t>>1), k-quad ((t&1)*4)
    const int  lm = tid >> 1;
    const int  lk = (tid & 1) * 4;
    const int  lr = row0 + lm;
    const bool lvalid = lr < NTRI;

    const float* pA0 = in;
    const float* pA1 = in;
    if (MODE == 0) {
        if (lvalid) {
            int b = lr / T; int t = lr - b * T;
            int2 ij = g_tri[t];
            pA0 = in + (size_t)(b * V + ij.x) * D + lk;
            pA1 = in + (size_t)(b * V + ij.y) * D + lk;
        }
    } else {
        pA0 = in + (size_t)lr * CIN + lk;   // only dereferenced when lvalid
    }

    if (tid < BM) {
        int r = row0 + tid;
        float w = 0.f;
        if (r < NTRI) {
            int b = r / T; int2 ij = g_tri[r - b * T];
            w = (ij.x == ij.y) ? 1.f : 2.f;
        }
        wrow[tid] = w;
    }

    const int ty = tid >> 4, tx = tid & 15;

    float acc[8][8];
    #pragma unroll
    for (int i = 0; i < 8; ++i)
        #pragma unroll
        for (int j = 0; j < 8; ++j) acc[i][j] = 0.f;

    const float* pW = W + (size_t)(n0 + lm) * CIN + lk;

    for (int k0 = 0; k0 < CIN; k0 += BK) {
        float4 av = make_float4(0.f, 0.f, 0.f, 0.f);
        if (lvalid) {
            if (MODE == 0) {
                float4 u = *(const float4*)(pA0 + k0);
                float4 v = *(const float4*)(pA1 + k0);
                av.x = fabsf(u.x - v.x); av.y = fabsf(u.y - v.y);
                av.z = fabsf(u.z - v.z); av.w = fabsf(u.w - v.w);
            } else {
                float4 u = *(const float4*)(pA0 + k0);
                float4 s = *(const float4*)(scale + k0 + lk);
                float4 h = *(const float4*)(shift + k0 + lk);
                av.x = lrelu(fmaf(u.x, s.x, h.x));
                av.y = lrelu(fmaf(u.y, s.y, h.y));
                av.z = lrelu(fmaf(u.z, s.z, h.z));
                av.w = lrelu(fmaf(u.w, s.w, h.w));
            }
        }
        float4 bv = *(const float4*)(pW + k0);

        __syncthreads();
        sA[lk + 0][lm] = av.x; sA[lk + 1][lm] = av.y;
        sA[lk + 2][lm] = av.z; sA[lk + 3][lm] = av.w;
        sB[lk + 0][lm] = bv.x; sB[lk + 1][lm] = bv.y;
        sB[lk + 2][lm] = bv.z; sB[lk + 3][lm] = bv.w;
        __syncthreads();

        #pragma unroll
        for (int kk = 0; kk < BK; ++kk) {
            float a[8], b8[8];
            *(float4*)&a[0]  = *(const float4*)&sA[kk][ty * 8];
            *(float4*)&a[4]  = *(const float4*)&sA[kk][ty * 8 + 4];
            *(float4*)&b8[0] = *(const float4*)&sB[kk][tx * 8];
            *(float4*)&b8[4] = *(const float4*)&sB[kk][tx * 8 + 4];
            #pragma unroll
            for (int i = 0; i < 8; ++i)
                #pragma unroll
                for (int j = 0; j < 8; ++j)
                    acc[i][j] = fmaf(a[i], b8[j], acc[i][j]);
        }
    }

    // Epilogue: bias, store, weighted stats
    float bcol[8];
    *(float4*)&bcol[0] = *(const float4*)(bias + n0 + tx * 8);
    *(float4*)&bcol[4] = *(const float4*)(bias + n0 + tx * 8 + 4);

    float ps[8], ps2[8];
    #pragma unroll
    for (int j = 0; j < 8; ++j) { ps[j] = 0.f; ps2[j] = 0.f; }

    #pragma unroll
    for (int i = 0; i < 8; ++i) {
        int r = row0 + ty * 8 + i;
        float w = wrow[ty * 8 + i];       // 0 for out-of-range rows
        float o[8];
        #pragma unroll
        for (int j = 0; j < 8; ++j) {
            float y = acc[i][j] + bcol[j];
            o[j] = y;
            ps[j]  = fmaf(w, y, ps[j]);
            ps2[j] = fmaf(w * y, y, ps2[j]);
        }
        if (r < NTRI) {
            float4* po = (float4*)(out + (size_t)r * COUT + n0 + tx * 8);
            po[0] = make_float4(o[0], o[1], o[2], o[3]);
            po[1] = make_float4(o[4], o[5], o[6], o[7]);
        }
    }

    #pragma unroll
    for (int j = 0; j < 8; ++j) red[ty][tx * 8 + j] = ps[j];
    __syncthreads();
    if (tid < BN) {
        float s = 0.f;
        #pragma unroll
        for (int q = 0; q < 16; ++q) s += red[q][tid];
        atomicAdd(&osum[n0 + tid], (double)s);
    }
    __syncthreads();
    #pragma unroll
    for (int j = 0; j < 8; ++j) red[ty][tx * 8 + j] = ps2[j];
    __syncthreads();
    if (tid < BN) {
        float s = 0.f;
        #pragma unroll
        for (int q = 0; q < 16; ++q) s += red[q][tid];
        atomicAdd(&osumsq[n0 + tid], (double)s);
    }
}

// ---------------------------------------------------------------------------
__global__ void k_bnfin(int layer, const float* __restrict__ g,
                        const float* __restrict__ be, int C) {
    int c = threadIdx.x;
    if (c < C) {
        double m = g_sum[layer][c] / (double)cfg::NFULL;
        double v = g_sumsq[layer][c] / (double)cfg::NFULL - m * m;
        float s = g[c] / sqrtf((float)v + cfg::EPS);
        g_scale[layer][c] = s;
        g_shift[layer][c] = be[c] - (float)m * s;
    }
}

// Final linear: logits[r] = dot(leaky(bn3(y3[r,:])), w4) + b4. One warp/row.
__global__ void k_final(const float* __restrict__ y, const float* __restrict__ w4,
                        const float* __restrict__ b4) {
    using namespace cfg;
    int warp = threadIdx.x >> 5, lane = threadIdx.x & 31;
    int r = blockIdx.x * 8 + warp;
    if (r >= NTRI) return;
    int c = lane * 4;
    float4 u = *(const float4*)(y + (size_t)r * H + c);
    float4 s = *(const float4*)(&g_scale[3][c]);
    float4 h = *(const float4*)(&g_shift[3][c]);
    float4 w = *(const float4*)(w4 + c);
    float d = lrelu(fmaf(u.x, s.x, h.x)) * w.x
            + lrelu(fmaf(u.y, s.y, h.y)) * w.y
            + lrelu(fmaf(u.z, s.z, h.z)) * w.z
            + lrelu(fmaf(u.w, s.w, h.w)) * w.w;
    #pragma unroll
    for (int o = 16; o > 0; o >>= 1) d += __shfl_xor_sync(0xffffffffu, d, o);
    if (lane == 0) g_logits[r] = d + b4[0];
}

// Softmax over j + exact stable top-K mask (rank-by-counting matches jax
// top_k tie-breaking: rank = #(val greater) + #(equal with smaller index)).
__global__ void k_softmax(float* __restrict__ outp) {
    using namespace cfg;
    __shared__ float Av[256];
    __shared__ float red[256];
    int b = blockIdx.x / V;
    int i = blockIdx.x - b * V;
    int tid = threadIdx.x;

    float v = -INFINITY;
    if (tid < V) {
        int j  = tid;
        int i2 = i < j ? i : j;
        int j2 = i < j ? j : i;
        int t  = i2 * V - (i2 * (i2 - 1)) / 2 + (j2 - i2);
        v = g_logits[b * T + t];
    }
    red[tid] = v;
    __syncthreads();
    for (int o = 128; o > 0; o >>= 1) {
        if (tid < o) red[tid] = fmaxf(red[tid], red[tid + o]);
        __syncthreads();
    }
    float mx = red[0];
    __syncthreads();

    float e = (tid < V) ? expf(v - mx) : 0.f;
    Av[tid]  = e;
    red[tid] = e;
    __syncthreads();
    for (int o = 128; o > 0; o >>= 1) {
        if (tid < o) red[tid] += red[tid + o];
        __syncthreads();
    }
    float inv = 1.f / red[0];

    if (tid < V) {
        float ej = Av[tid];
        int rank = 0;
        for (int l = 0; l < V; ++l) {
            float el = Av[l];
            rank += (el > ej) || (el == ej && l < tid);
        }
        outp[(size_t)(b * V + i) * V + tid] = (rank < KTOP) ? ej * inv : 0.f;
    }
}

// ---------------------------------------------------------------------------
extern "C" void kernel_launch(void* const* d_in, const int* in_sizes, int n_in,
                              void* d_out, int out_size) {
    using namespace cfg;
    const float* x = (const float*)d_in[0];
    const float* w[4]; const float* bb[4]; const float* gm[4]; const float* be[4];
    for (int i = 0; i < 4; ++i) {
        w[i]  = (const float*)d_in[1 + 4 * i];
        bb[i] = (const float*)d_in[2 + 4 * i];
        gm[i] = (const float*)d_in[3 + 4 * i];
        be[i] = (const float*)d_in[4 + 4 * i];
    }
    const float* w4 = (const float*)d_in[17];
    const float* b4 = (const float*)d_in[18];
    float* out = (float*)d_out;

    float *bufA, *bufB, *scl, *shf;
    double *sum, *sumsq;
    cudaGetSymbolAddress((void**)&bufA, g_bufA);
    cudaGetSymbolAddress((void**)&bufB, g_bufB);
    cudaGetSymbolAddress((void**)&scl,  g_scale);
    cudaGetSymbolAddress((void**)&shf,  g_shift);
    cudaGetSymbolAddress((void**)&sum,  g_sum);
    cudaGetSymbolAddress((void**)&sumsq, g_sumsq);

    const int mt = (NTRI + 127) / 128;   // 1269 row tiles

    k_init<<<1, 1024>>>();
    k_tri<<<V, 256>>>();

    k_gemm<256, 256, 0><<<dim3(mt, 2), 256>>>(x,    w[0], bb[0], nullptr, nullptr,
                                              bufA, sum,       sumsq);
    k_bnfin<<<1, 256>>>(0, gm[0], be[0], 256);

    k_gemm<256, 256, 1><<<dim3(mt, 2), 256>>>(bufA, w[1], bb[1], scl,       shf,
                                              bufB, sum + 256, sumsq + 256);
    k_bnfin<<<1, 256>>>(1, gm[1], be[1], 256);

    k_gemm<256, 128, 1><<<dim3(mt, 1), 256>>>(bufB, w[2], bb[2], scl + 256, shf + 256,
                                              bufA, sum + 512, sumsq + 512);
    k_bnfin<<<1, 256>>>(2, gm[2], be[2], 128);

    k_gemm<128, 128, 1><<<dim3(mt, 1), 256>>>(bufA, w[3], bb[3], scl + 512, shf + 512,
                                              bufB, sum + 768, sumsq + 768);
    k_bnfin<<<1, 256>>>(3, gm[3], be[3], 128);

    k_final<<<NTRI / 8, 256>>>(bufB, w4, b4);
    k_softmax<<<B * V, 256>>>(out);
}

// round 8
// speedup vs baseline: 3.4714x; 3.4714x over previous
#include <cuda_runtime.h>
#include <cuda_bf16.h>
#include <math.h>
#include <stdint.h>

// ============================================================================
// pairwise |x_i - x_j| -> 4x(1x1conv + BN(train) + LeakyReLU) -> linear
// -> softmax(axis=2) -> top-K scatter mask.
// Symmetry: logits[b,i,j]==logits[b,j,i] -> compute upper triangle only.
// GEMMs via mma.sync bf16 (sm_103-safe legacy tensor path), bf16x2 split:
//   C = Ah*Bh + Ah*Bl + Al*Bh  (fp32 accumulate)  -> ~2^-16 element error.
// ============================================================================

namespace cfg {
constexpr int B = 8, V = 201, D = 256, H = 128;
constexpr int T = V * (V + 1) / 2;     // 20301
constexpr int NTRI = B * T;            // 162408
constexpr int NFULL = B * V * V;       // 323208 (BN statistics population)
constexpr int KTOP = 100;
constexpr float EPS = 1e-5f;
constexpr float SLOPE = 0.01f;
constexpr int MT = (NTRI + 127) / 128; // 1269 row tiles
}

// Scratch (static device globals -- no allocations allowed)
__device__ float  g_bufA[(size_t)cfg::NTRI * 256];
__device__ float  g_bufB[(size_t)cfg::NTRI * 256];
__device__ float  g_logits[cfg::NTRI];
__device__ double g_sum[4][256];
__device__ double g_sumsq[4][256];
__device__ float  g_scale[4][256];
__device__ float  g_shift[4][256];
__device__ int2   g_tri[cfg::T];
// split weights: L0 @0 (65536), L1 @65536, L2 @131072 (32768), L3 @163840 (16384)
__device__ __nv_bfloat16 g_whi[180224];
__device__ __nv_bfloat16 g_wlo[180224];

__device__ __forceinline__ float lrelu(float v) {
    return v >= 0.f ? v : cfg::SLOPE * v;
}

__device__ __forceinline__ uint32_t smem_u32(const void* p) {
    uint32_t a;
    asm("{ .reg .u64 t; cvta.to.shared.u64 t, %1; cvt.u32.u64 %0, t; }"
        : "=r"(a) : "l"(p));
    return a;
}

__device__ __forceinline__ void ldmx4(uint32_t* r, uint32_t addr) {
    asm volatile("ldmatrix.sync.aligned.m8n8.x4.shared.b16 {%0,%1,%2,%3}, [%4];"
        : "=r"(r[0]), "=r"(r[1]), "=r"(r[2]), "=r"(r[3]) : "r"(addr));
}

__device__ __forceinline__ void mma16816(float* c, const uint32_t* a,
                                         const uint32_t* b) {
    asm volatile(
        "mma.sync.aligned.m16n8k16.row.col.f32.bf16.bf16.f32 "
        "{%0,%1,%2,%3}, {%4,%5,%6,%7}, {%8,%9}, {%0,%1,%2,%3};"
        : "+f"(c[0]), "+f"(c[1]), "+f"(c[2]), "+f"(c[3])
        : "r"(a[0]), "r"(a[1]), "r"(a[2]), "r"(a[3]), "r"(b[0]), "r"(b[1]));
}

__device__ __forceinline__ uint32_t packsplit(float a, float b, uint32_t* lo) {
    __nv_bfloat16 ha = __float2bfloat16(a), hb = __float2bfloat16(b);
    __nv_bfloat16 la = __float2bfloat16(a - __bfloat162float(ha));
    __nv_bfloat16 lb = __float2bfloat16(b - __bfloat162float(hb));
    *lo = (uint32_t)__bfloat16_as_ushort(la) | ((uint32_t)__bfloat16_as_ushort(lb) << 16);
    return (uint32_t)__bfloat16_as_ushort(ha) | ((uint32_t)__bfloat16_as_ushort(hb) << 16);
}

// ---------------------------------------------------------------------------
__global__ void k_init() {
    int t = blockIdx.x * blockDim.x + threadIdx.x;
    if (t < 1024) { ((double*)g_sum)[t] = 0.0; ((double*)g_sumsq)[t] = 0.0; }
}

__global__ void k_tri() {
    int i = blockIdx.x;
    int base = i * cfg::V - (i * (i - 1)) / 2;
    for (int j = i + threadIdx.x; j < cfg::V; j += blockDim.x)
        g_tri[base + (j - i)] = make_int2(i, j);
}

// Pre-split all layer weights into bf16 hi/lo planes.
__global__ void k_wsplit(const float* __restrict__ w0, const float* __restrict__ w1,
                         const float* __restrict__ w2, const float* __restrict__ w3) {
    int t = blockIdx.x * blockDim.x + threadIdx.x;
    const float* src; int off, idx;
    if      (t < 65536)  { src = w0; off = 0;      idx = t; }
    else if (t < 131072) { src = w1; off = 65536;  idx = t - 65536; }
    else if (t < 163840) { src = w2; off = 131072; idx = t - 131072; }
    else if (t < 180224) { src = w3; off = 163840; idx = t - 163840; }
    else return;
    float v = src[idx];
    __nv_bfloat16 h = __float2bfloat16(v);
    g_whi[off + idx] = h;
    g_wlo[off + idx] = __float2bfloat16(v - __bfloat162float(h));
}

// ---------------------------------------------------------------------------
// mma.sync fused GEMM layer. CTA tile 128 rows x 128 cols; 8 warps in 2x4 grid,
// each warp 64x32 via m16n8k16. K chunks of 32. bf16 hi/lo split, 3 mma terms.
// MODE 0: A = |x[b,i,:] - x[b,j,:]|   MODE 1: A = leaky(in*scale + shift)
// Epilogue: +bias, fp32 store, weighted BN stats (diag w=1, offdiag w=2).
// SMEM rows padded to 40 bf16 (80 B): ldmatrix conflict-free.
// ---------------------------------------------------------------------------
template<int CIN, int COUT, int MODE>
__global__ void __launch_bounds__(256, 2)
k_mma(const float* __restrict__ in,
      const __nv_bfloat16* __restrict__ whi, const __nv_bfloat16* __restrict__ wlo,
      const float* __restrict__ bias,
      const float* __restrict__ scale, const float* __restrict__ shift,
      float* __restrict__ out, double* __restrict__ osum, double* __restrict__ osumsq)
{
    using namespace cfg;
    __shared__ __align__(16) uint16_t sAh[128 * 40];
    __shared__ __align__(16) uint16_t sAl[128 * 40];
    __shared__ __align__(16) uint16_t sBh[128 * 40];
    __shared__ __align__(16) uint16_t sBl[128 * 40];
    __shared__ float wrow[128];

    const int tid = threadIdx.x, lane = tid & 31, wid = tid >> 5;
    const int row0 = blockIdx.x * 128, n0 = blockIdx.y * 128;
    const int wy = wid & 1, wx = wid >> 1;

    if (tid < 128) {
        int r = row0 + tid; float w = 0.f;
        if (r < NTRI) { int b = r / T; int2 ij = g_tri[r - b * T];
                        w = (ij.x == ij.y) ? 1.f : 2.f; }
        wrow[tid] = w;
    }

    // ---- producer setup: thread -> rows {pr0, pr0+64}, k-eighth kq ----
    const int pr0 = tid >> 2;
    const int kq = (tid & 3) * 8;
    const float* paA[2]; const float* paB[2];
    const __nv_bfloat16* pwh[2]; const __nv_bfloat16* pwl[2];
    #pragma unroll
    for (int i = 0; i < 2; ++i) {
        int r = row0 + pr0 + i * 64; if (r >= NTRI) r = NTRI - 1;  // clamp: w=0 kills stats
        if (MODE == 0) {
            int b = r / T; int2 ij = g_tri[r - b * T];
            paA[i] = in + (size_t)(b * V + ij.x) * D + kq;
            paB[i] = in + (size_t)(b * V + ij.y) * D + kq;
        } else {
            paA[i] = in + (size_t)r * CIN + kq;
        }
        int n = n0 + pr0 + i * 64;
        pwh[i] = whi + (size_t)n * CIN + kq;
        pwl[i] = wlo + (size_t)n * CIN + kq;
    }

    // ---- ldmatrix lane addressing (conflict-free with 80 B row stride) ----
    const int adr = lane & 15, adk = (lane >> 4) * 8;                 // A: m,k
    const int bdn = (lane & 7) + ((lane & 16) ? 8 : 0);               // B: n
    const int bdk = (lane & 8) ? 8 : 0;                               // B: k
    const uint32_t aHb = smem_u32(&sAh[(wy * 64 + adr) * 40 + adk]);
    const uint32_t aLb = smem_u32(&sAl[(wy * 64 + adr) * 40 + adk]);
    const uint32_t bHb = smem_u32(&sBh[(wx * 32 + bdn) * 40 + bdk]);
    const uint32_t bLb = smem_u32(&sBl[(wx * 32 + bdn) * 40 + bdk]);

    float acc[4][4][4];
    #pragma unroll
    for (int m = 0; m < 4; ++m)
        #pragma unroll
        for (int n = 0; n < 4; ++n)
            #pragma unroll
            for (int q = 0; q < 4; ++q) acc[m][n][q] = 0.f;

    constexpr int NCH = CIN / 32;
    for (int c = 0; c < NCH; ++c) {
        const int k0 = c * 32;
        __syncthreads();   // prev chunk's consumers done before overwrite
        #pragma unroll
        for (int i = 0; i < 2; ++i) {
            const int row = pr0 + i * 64;
            float v[8];
            float4 u0 = *(const float4*)(paA[i] + k0);
            float4 u1 = *(const float4*)(paA[i] + k0 + 4);
            if (MODE == 0) {
                float4 z0 = *(const float4*)(paB[i] + k0);
                float4 z1 = *(const float4*)(paB[i] + k0 + 4);
                v[0] = fabsf(u0.x - z0.x); v[1] = fabsf(u0.y - z0.y);
                v[2] = fabsf(u0.z - z0.z); v[3] = fabsf(u0.w - z0.w);
                v[4] = fabsf(u1.x - z1.x); v[5] = fabsf(u1.y - z1.y);
                v[6] = fabsf(u1.z - z1.z); v[7] = fabsf(u1.w - z1.w);
            } else {
                float4 sc0 = *(const float4*)(scale + k0 + kq);
                float4 sc1 = *(const float4*)(scale + k0 + kq + 4);
                float4 sh0 = *(const float4*)(shift + k0 + kq);
                float4 sh1 = *(const float4*)(shift + k0 + kq + 4);
                v[0] = lrelu(fmaf(u0.x, sc0.x, sh0.x));
                v[1] = lrelu(fmaf(u0.y, sc0.y, sh0.y));
                v[2] = lrelu(fmaf(u0.z, sc0.z, sh0.z));
                v[3] = lrelu(fmaf(u0.w, sc0.w, sh0.w));
                v[4] = lrelu(fmaf(u1.x, sc1.x, sh1.x));
                v[5] = lrelu(fmaf(u1.y, sc1.y, sh1.y));
                v[6] = lrelu(fmaf(u1.z, sc1.z, sh1.z));
                v[7] = lrelu(fmaf(u1.w, sc1.w, sh1.w));
            }
            uint32_t hi[4], lo[4];
            #pragma unroll
            for (int j = 0; j < 4; ++j)
                hi[j] = packsplit(v[2 * j], v[2 * j + 1], &lo[j]);
            *(uint4*)&sAh[row * 40 + kq] = make_uint4(hi[0], hi[1], hi[2], hi[3]);
            *(uint4*)&sAl[row * 40 + kq] = make_uint4(lo[0], lo[1], lo[2], lo[3]);
            *(uint4*)&sBh[row * 40 + kq] = *(const uint4*)(pwh[i] + k0);
            *(uint4*)&sBl[row * 40 + kq] = *(const uint4*)(pwl[i] + k0);
        }
        __syncthreads();

        #pragma unroll
        for (int ks = 0; ks < 2; ++ks) {          // k-steps of 16 (byte off ks*32)
            uint32_t bh[2][4], bl[2][4];
            #pragma unroll
            for (int np = 0; np < 2; ++np) {
                ldmx4(bh[np], bHb + np * 16 * 80 + ks * 32);
                ldmx4(bl[np], bLb + np * 16 * 80 + ks * 32);
            }
            #pragma unroll
            for (int mt = 0; mt < 4; ++mt) {
                uint32_t ah[4], al[4];
                ldmx4(ah, aHb + mt * 16 * 80 + ks * 32);
                ldmx4(al, aLb + mt * 16 * 80 + ks * 32);
                #pragma unroll
                for (int nt = 0; nt < 4; ++nt) {
                    const uint32_t* ph = &bh[nt >> 1][(nt & 1) * 2];
                    const uint32_t* pl = &bl[nt >> 1][(nt & 1) * 2];
                    mma16816(acc[mt][nt], ah, ph);
                    mma16816(acc[mt][nt], ah, pl);
                    mma16816(acc[mt][nt], al, ph);
                }
            }
        }
    }

    // ---------------- epilogue ----------------
    float ps[8], ps2[8];
    #pragma unroll
    for (int j = 0; j < 8; ++j) { ps[j] = 0.f; ps2[j] = 0.f; }

    #pragma unroll
    for (int nt = 0; nt < 4; ++nt) {
        const int col = n0 + wx * 32 + nt * 8 + (lane & 3) * 2;
        const float b0 = bias[col], b1 = bias[col + 1];
        #pragma unroll
        for (int mt = 0; mt < 4; ++mt) {
            const int lr = wy * 64 + mt * 16 + (lane >> 2);
            const int r1 = row0 + lr, r2 = r1 + 8;
            const float w1 = wrow[lr], w2 = wrow[lr + 8];
            float y0 = acc[mt][nt][0] + b0, y1 = acc[mt][nt][1] + b1;
            float y2 = acc[mt][nt][2] + b0, y3 = acc[mt][nt][3] + b1;
            if (r1 < NTRI) { float2 o = make_float2(y0, y1);
                *(float2*)(out + (size_t)r1 * COUT + col) = o; }
            if (r2 < NTRI) { float2 o = make_float2(y2, y3);
                *(float2*)(out + (size_t)r2 * COUT + col) = o; }
            ps[nt * 2]     += w1 * y0 + w2 * y2;
            ps[nt * 2 + 1] += w1 * y1 + w2 * y3;
            ps2[nt * 2]     += w1 * y0 * y0 + w2 * y2 * y2;
            ps2[nt * 2 + 1] += w1 * y1 * y1 + w2 * y3 * y3;
        }
    }
    #pragma unroll
    for (int off = 4; off <= 16; off <<= 1)
        #pragma unroll
        for (int j = 0; j < 8; ++j) {
            ps[j]  += __shfl_xor_sync(0xffffffffu, ps[j],  off);
            ps2[j] += __shfl_xor_sync(0xffffffffu, ps2[j], off);
        }
    if (lane < 4) {
        #pragma unroll
        for (int nt = 0; nt < 4; ++nt) {
            const int col = n0 + wx * 32 + nt * 8 + lane * 2;
            atomicAdd(&osum[col],       (double)ps[nt * 2]);
            atomicAdd(&osum[col + 1],   (double)ps[nt * 2 + 1]);
            atomicAdd(&osumsq[col],     (double)ps2[nt * 2]);
            atomicAdd(&osumsq[col + 1], (double)ps2[nt * 2 + 1]);
        }
    }
}

// ---------------------------------------------------------------------------
__global__ void k_bnfin(int layer, const float* __restrict__ g,
                        const float* __restrict__ be, int C) {
    int c = threadIdx.x;
    if (c < C) {
        double m = g_sum[layer][c] / (double)cfg::NFULL;
        double v = g_sumsq[layer][c] / (double)cfg::NFULL - m * m;
        float s = g[c] / sqrtf((float)v + cfg::EPS);
        g_scale[layer][c] = s;
        g_shift[layer][c] = be[c] - (float)m * s;
    }
}

// logits[r] = dot(leaky(bn3(y3[r,:])), w4) + b4. One warp per row.
__global__ void k_final(const float* __restrict__ y, const float* __restrict__ w4,
                        const float* __restrict__ b4) {
    using namespace cfg;
    int warp = threadIdx.x >> 5, lane = threadIdx.x & 31;
    int r = blockIdx.x * 8 + warp;
    if (r >= NTRI) return;
    int c = lane * 4;
    float4 u = *(const float4*)(y + (size_t)r * H + c);
    float4 s = *(const float4*)(&g_scale[3][c]);
    float4 h = *(const float4*)(&g_shift[3][c]);
    float4 w = *(const float4*)(w4 + c);
    float d = lrelu(fmaf(u.x, s.x, h.x)) * w.x
            + lrelu(fmaf(u.y, s.y, h.y)) * w.y
            + lrelu(fmaf(u.z, s.z, h.z)) * w.z
            + lrelu(fmaf(u.w, s.w, h.w)) * w.w;
    #pragma unroll
    for (int o = 16; o > 0; o >>= 1) d += __shfl_xor_sync(0xffffffffu, d, o);
    if (lane == 0) g_logits[r] = d + b4[0];
}

// softmax over j + stable top-K mask (rank by counting, matches jax tie-break)
__global__ void k_softmax(float* __restrict__ outp) {
    using namespace cfg;
    __shared__ float Av[256];
    __shared__ float red[256];
    int b = blockIdx.x / V;
    int i = blockIdx.x - b * V;
    int tid = threadIdx.x;

    float v = -INFINITY;
    if (tid < V) {
        int j  = tid;
        int i2 = i < j ? i : j;
        int j2 = i < j ? j : i;
        int t  = i2 * V - (i2 * (i2 - 1)) / 2 + (j2 - i2);
        v = g_logits[b * T + t];
    }
    red[tid] = v;
    __syncthreads();
    for (int o = 128; o > 0; o >>= 1) {
        if (tid < o) red[tid] = fmaxf(red[tid], red[tid + o]);
        __syncthreads();
    }
    float mx = red[0];
    __syncthreads();

    float e = (tid < V) ? expf(v - mx) : 0.f;
    Av[tid]  = e;
    red[tid] = e;
    __syncthreads();
    for (int o = 128; o > 0; o >>= 1) {
        if (tid < o) red[tid] += red[tid + o];
        __syncthreads();
    }
    float inv = 1.f / red[0];

    if (tid < V) {
        float ej = Av[tid];
        int rank = 0;
        for (int l = 0; l < V; ++l) {
            float el = Av[l];
            rank += (el > ej) || (el == ej && l < tid);
        }
        outp[(size_t)(b * V + i) * V + tid] = (rank < KTOP) ? ej * inv : 0.f;
    }
}

// ---------------------------------------------------------------------------
extern "C" void kernel_launch(void* const* d_in, const int* in_sizes, int n_in,
                              void* d_out, int out_size) {
    using namespace cfg;
    const float* x = (const float*)d_in[0];
    const float* w[4]; const float* bb[4]; const float* gm[4]; const float* be[4];
    for (int i = 0; i < 4; ++i) {
        w[i]  = (const float*)d_in[1 + 4 * i];
        bb[i] = (const float*)d_in[2 + 4 * i];
        gm[i] = (const float*)d_in[3 + 4 * i];
        be[i] = (const float*)d_in[4 + 4 * i];
    }
    const float* w4 = (const float*)d_in[17];
    const float* b4 = (const float*)d_in[18];
    float* out = (float*)d_out;

    float *bufA, *bufB, *scl, *shf;
    double *sum, *sumsq;
    __nv_bfloat16 *whi, *wlo;
    cudaGetSymbolAddress((void**)&bufA, g_bufA);
    cudaGetSymbolAddress((void**)&bufB, g_bufB);
    cudaGetSymbolAddress((void**)&scl,  g_scale);
    cudaGetSymbolAddress((void**)&shf,  g_shift);
    cudaGetSymbolAddress((void**)&sum,  g_sum);
    cudaGetSymbolAddress((void**)&sumsq, g_sumsq);
    cudaGetSymbolAddress((void**)&whi,  g_whi);
    cudaGetSymbolAddress((void**)&wlo,  g_wlo);

    k_init<<<1, 1024>>>();
    k_tri<<<V, 256>>>();
    k_wsplit<<<704, 256>>>(w[0], w[1], w[2], w[3]);

    k_mma<256, 256, 0><<<dim3(MT, 2), 256>>>(
        x, whi, wlo, bb[0], nullptr, nullptr, bufA, sum, sumsq);
    k_bnfin<<<1, 256>>>(0, gm[0], be[0], 256);

    k_mma<256, 256, 1><<<dim3(MT, 2), 256>>>(
        bufA, whi + 65536, wlo + 65536, bb[1], scl, shf, bufB, sum + 256, sumsq + 256);
    k_bnfin<<<1, 256>>>(1, gm[1], be[1], 256);

    k_mma<256, 128, 1><<<dim3(MT, 1), 256>>>(
        bufB, whi + 131072, wlo + 131072, bb[2], scl + 256, shf + 256,
        bufA, sum + 512, sumsq + 512);
    k_bnfin<<<1, 256>>>(2, gm[2], be[2], 128);

    k_mma<128, 128, 1><<<dim3(MT, 1), 256>>>(
        bufA, whi + 163840, wlo + 163840, bb[3], scl + 512, shf + 512,
        bufB, sum + 768, sumsq + 768);
    k_bnfin<<<1, 256>>>(3, gm[3], be[3], 128);

    k_final<<<NTRI / 8, 256>>>(bufB, w4, b4);
    k_softmax<<<B * V, 256>>>(out);
}